// round 1
// baseline (speedup 1.0000x reference)
#include <cuda_runtime.h>
#include <cuda_bf16.h>
#include <cstdint>

// Problem constants
#define BATCH 16
#define CIN   64
#define COUT  128
#define HH    32
#define WW    32
#define HP    34            // padded
#define L     (HH*WW)       // 1024 pixels per image
#define KTAPS 9
#define KTOT  (KTAPS*CIN)   // 576

// ---- device scratch (no allocations allowed) ----
__device__ unsigned g_maxx;
__device__ unsigned g_maxw;
__device__ float    g_xscale;
__device__ float    g_wscale;
__device__ float    g_oscale;
__device__ signed char g_qxp[BATCH*HP*HP*CIN];     // NHWC, zero-padded  (1,183,744 B)
__device__ signed char g_qw [KTAPS*COUT*CIN];      // [tap][cout][cin]   (73,728 B)

// ---------------------------------------------------------------------------
// 1) zero scratch: padded qx buffer + the two max accumulators
// ---------------------------------------------------------------------------
__global__ void kzero(int n4) {
    int i = blockIdx.x * blockDim.x + threadIdx.x;
    if (i == 0) { g_maxx = 0u; g_maxw = 0u; }
    if (i < n4) reinterpret_cast<int4*>(g_qxp)[i] = make_int4(0,0,0,0);
}

// ---------------------------------------------------------------------------
// 2) max |v| reduction (uint-bit max == float max for non-negative floats)
// ---------------------------------------------------------------------------
__global__ void kmaxabs(const float4* __restrict__ p, int n4, int sel) {
    float m = 0.f;
    for (int i = blockIdx.x * blockDim.x + threadIdx.x; i < n4;
         i += gridDim.x * blockDim.x) {
        float4 v = p[i];
        m = fmaxf(m, fmaxf(fmaxf(fabsf(v.x), fabsf(v.y)),
                           fmaxf(fabsf(v.z), fabsf(v.w))));
    }
    #pragma unroll
    for (int o = 16; o; o >>= 1) m = fmaxf(m, __shfl_xor_sync(0xffffffffu, m, o));
    if ((threadIdx.x & 31) == 0) {
        unsigned bits = __float_as_uint(m);
        atomicMax(sel == 0 ? &g_maxx : &g_maxw, bits);
    }
}

__global__ void kscale() {
    float xs = __fdiv_rn(__uint_as_float(g_maxx), 127.0f);
    float ws = __fdiv_rn(__uint_as_float(g_maxw), 127.0f);
    g_xscale = xs; g_wscale = ws; g_oscale = __fmul_rn(xs, ws);
}

// ---------------------------------------------------------------------------
// 3) quantize input -> NHWC padded int8.  thread = (b, c4, pix)
// ---------------------------------------------------------------------------
__global__ void kquantx(const float* __restrict__ x) {
    int idx = blockIdx.x * blockDim.x + threadIdx.x;      // 16*16*1024
    if (idx >= BATCH * (CIN/4) * L) return;
    int pix = idx & (L - 1);
    int c4  = (idx >> 10) & 15;
    int b   = idx >> 14;
    int y = pix >> 5, xcol = pix & 31;
    float xs = g_xscale;
    char4 q;
    #pragma unroll
    for (int j = 0; j < 4; j++) {
        float v = x[((b*CIN + c4*4 + j) * L) + pix];
        float r = rintf(__fdiv_rn(v, xs));
        r = fminf(fmaxf(r, -127.f), 127.f);
        ((signed char*)&q)[j] = (signed char)(int)r;
    }
    *reinterpret_cast<char4*>(
        g_qxp + (((b*HP + y + 1)*HP + (xcol + 1))*CIN + c4*4)) = q;
}

// weight [cout][cin][kh][kw] -> g_qw[tap][cout][cin]
__global__ void kquantw(const float* __restrict__ w) {
    int idx = blockIdx.x * blockDim.x + threadIdx.x;
    if (idx >= KTAPS * COUT * CIN) return;
    int tap  = idx / (COUT * CIN);
    int rem  = idx - tap * COUT * CIN;
    int cout = rem / CIN, cin = rem % CIN;
    float v = w[(cout*CIN + cin)*KTAPS + tap];
    float r = rintf(__fdiv_rn(v, g_wscale));
    r = fminf(fmaxf(r, -127.f), 127.f);
    g_qw[idx] = (signed char)(int)r;
}

// ---------------------------------------------------------------------------
// 4) int8 GEMM-conv, mma.sync m16n8k32 s8s8s32
//    block = 128 pixels (4 image rows of one batch) x 128 couts
//    SMEM: full weight [9][128] rows (80B stride) + A tile [128] rows (80B)
// ---------------------------------------------------------------------------
#define ROWB 80           // padded smem row stride (bytes) -> conflict-free frags
#define BS_BYTES (KTAPS*COUT*ROWB)     // 92160
#define AS_BYTES (128*ROWB)            // 10240

__device__ __forceinline__ void mma_s8(int d[4], const unsigned a[4],
                                       unsigned b0, unsigned b1) {
    asm volatile(
      "mma.sync.aligned.m16n8k32.row.col.s32.s8.s8.s32 "
      "{%0,%1,%2,%3}, {%4,%5,%6,%7}, {%8,%9}, {%0,%1,%2,%3};\n"
      : "+r"(d[0]), "+r"(d[1]), "+r"(d[2]), "+r"(d[3])
      : "r"(a[0]), "r"(a[1]), "r"(a[2]), "r"(a[3]), "r"(b0), "r"(b1));
}

__global__ void __launch_bounds__(256, 1)
kgemm(const float* __restrict__ bias, float* __restrict__ out) {
    extern __shared__ char sm[];
    char* Bs = sm;              // [9*128][80]
    char* As = sm + BS_BYTES;   // [128][80]

    const int tid   = threadIdx.x;
    const int wid   = tid >> 5;
    const int lane  = tid & 31;
    const int g     = lane >> 2;     // groupID
    const int tg    = lane & 3;      // thread-in-group
    const int warpM = wid >> 1;      // 0..3  -> 32 rows each
    const int warpN = wid & 1;       // 0..1  -> 64 couts each

    const int bi    = blockIdx.x >> 3;       // batch
    const int ytile = blockIdx.x & 7;        // 4 image rows
    const int l0    = ytile * 128;

    // stage full weight tile once
    for (int r = tid; r < KTAPS * COUT; r += 256) {
        const int4* s = reinterpret_cast<const int4*>(g_qw + r * CIN);
        int4* d = reinterpret_cast<int4*>(Bs + r * ROWB);
        d[0] = s[0]; d[1] = s[1]; d[2] = s[2]; d[3] = s[3];
    }

    int acc[2][8][4];
    #pragma unroll
    for (int mi = 0; mi < 2; mi++)
        #pragma unroll
        for (int nb = 0; nb < 8; nb++)
            #pragma unroll
            for (int r = 0; r < 4; r++) acc[mi][nb][r] = 0;

    const int arow = tid >> 1, ahalf = tid & 1;
    const int ay = ytile * 4 + (arow >> 5);
    const int ax = arow & 31;

    for (int tap = 0; tap < KTAPS; tap++) {
        const int kh = tap / 3, kw = tap % 3;
        __syncthreads();
        {   // stage A: 128 rows x 64B from padded NHWC
            const int4* s = reinterpret_cast<const int4*>(
                g_qxp + (((bi*HP + ay + kh)*HP + (ax + kw))*CIN)) + ahalf*2;
            int4* d = reinterpret_cast<int4*>(As + arow * ROWB) + ahalf*2;
            d[0] = s[0]; d[1] = s[1];
        }
        __syncthreads();

        #pragma unroll
        for (int kk = 0; kk < 2; kk++) {
            const int ko = kk * 32;
            unsigned a[2][4];
            #pragma unroll
            for (int mi = 0; mi < 2; mi++) {
                const int rb = warpM*32 + mi*16 + g;
                a[mi][0] = *reinterpret_cast<const unsigned*>(As + rb*ROWB     + ko + tg*4);
                a[mi][1] = *reinterpret_cast<const unsigned*>(As + (rb+8)*ROWB + ko + tg*4);
                a[mi][2] = *reinterpret_cast<const unsigned*>(As + rb*ROWB     + ko + 16 + tg*4);
                a[mi][3] = *reinterpret_cast<const unsigned*>(As + (rb+8)*ROWB + ko + 16 + tg*4);
            }
            #pragma unroll
            for (int nb = 0; nb < 8; nb++) {
                const int n = warpN*64 + nb*8 + g;
                const char* bp = Bs + (tap*COUT + n)*ROWB + ko + tg*4;
                unsigned b0 = *reinterpret_cast<const unsigned*>(bp);
                unsigned b1 = *reinterpret_cast<const unsigned*>(bp + 16);
                mma_s8(acc[0][nb], a[0], b0, b1);
                mma_s8(acc[1][nb], a[1], b0, b1);
            }
        }
    }

    // epilogue: out[b][cout][l] = scale*acc + bias[cout]
    const float scale = g_oscale;
    #pragma unroll
    for (int mi = 0; mi < 2; mi++) {
        #pragma unroll
        for (int nb = 0; nb < 8; nb++) {
            const int n   = warpN*64 + nb*8 + tg*2;
            const float bz0 = bias[n], bz1 = bias[n+1];
            #pragma unroll
            for (int r = 0; r < 4; r++) {
                const int row = warpM*32 + mi*16 + g + ((r >> 1) * 8);
                const int col = n + (r & 1);
                out[(bi*COUT + col)*L + l0 + row] =
                    scale * (float)acc[mi][nb][r] + ((r & 1) ? bz1 : bz0);
            }
        }
    }
}

// ---------------------------------------------------------------------------
extern "C" void kernel_launch(void* const* d_in, const int* in_sizes, int n_in,
                              void* d_out, int out_size) {
    const float* x  = (const float*)d_in[0];   // [16,64,32,32]
    const float* w  = (const float*)d_in[1];   // [128,64,3,3]
    const float* bs = (const float*)d_in[2];   // [128]
    float* out = (float*)d_out;                // [16,128,32,32]

    static_assert(BS_BYTES + AS_BYTES == 102400, "smem layout");
    cudaFuncSetAttribute(kgemm, cudaFuncAttributeMaxDynamicSharedMemorySize,
                         BS_BYTES + AS_BYTES);

    const int qx4 = (BATCH*HP*HP*CIN) / 16;                    // 73984 int4
    kzero<<<(qx4 + 255)/256, 256>>>(qx4);
    kmaxabs<<<256, 256>>>((const float4*)x, BATCH*CIN*L/4, 0);
    kmaxabs<<<72, 256>>>((const float4*)w, KTAPS*COUT*CIN/4, 1);
    kscale<<<1, 1>>>();
    kquantx<<<(BATCH*(CIN/4)*L + 255)/256, 256>>>(x);
    kquantw<<<(KTAPS*COUT*CIN + 255)/256, 256>>>(w);
    kgemm<<<BATCH*8, 256, BS_BYTES + AS_BYTES>>>(bs, out);
}